// round 1
// baseline (speedup 1.0000x reference)
#include <cuda_runtime.h>
#include <math.h>

// Problem shapes (fixed by the dataset)
#define N_SRC 8
#define B 4
#define T 2048
#define H 2048
#define THREADS 512          // H / 4 floats per thread
#define EPS 1e-6f

// Per-n constant: (w_query[pos] . key_pos_bias[n]) / sqrt(H)
__device__ float g_cbias[N_SRC];

// ---------------------------------------------------------------------------
// Prelude: compute g_cbias[n] = dot(q, bias_n) / sqrt(H).  8 blocks x 256 thr.
// ---------------------------------------------------------------------------
__global__ void cbias_kernel(const float* __restrict__ wq,
                             const float* __restrict__ bias,
                             const int* __restrict__ pos_ptr) {
    const int n = blockIdx.x;
    const int pos = pos_ptr ? *pos_ptr : N_SRC;
    const float* q  = wq   + (size_t)pos * H;
    const float* bn = bias + (size_t)n   * H;

    float s = 0.f;
    for (int i = threadIdx.x; i < H; i += blockDim.x)
        s += q[i] * bn[i];

    #pragma unroll
    for (int o = 16; o; o >>= 1) s += __shfl_xor_sync(0xffffffffu, s, o);

    __shared__ float sm[32];
    if ((threadIdx.x & 31) == 0) sm[threadIdx.x >> 5] = s;
    __syncthreads();
    if (threadIdx.x < 32) {
        const int nw = blockDim.x >> 5;
        float v = (threadIdx.x < nw) ? sm[threadIdx.x] : 0.f;
        #pragma unroll
        for (int o = 16; o; o >>= 1) v += __shfl_xor_sync(0xffffffffu, v, o);
        if (threadIdx.x == 0) g_cbias[n] = v * rsqrtf((float)H);
    }
}

// ---------------------------------------------------------------------------
// Main kernel: one CTA per (b,t).  Single pass over values:
//   - hold 8 rows (8 x float4/thread) in registers
//   - block-reduce {sum(v^2), q.v} per n
//   - score_n = (q.v)*rsqrt(mean(v^2)+eps)/sqrt(H) + cbias_n
//   - softmax over n, weighted sum -> routed; alpha -> second output region
// ---------------------------------------------------------------------------
__global__ __launch_bounds__(THREADS)
void router_kernel(const float* __restrict__ values,
                   const float* __restrict__ wq,
                   const int* __restrict__ pos_ptr,
                   float* __restrict__ out_routed,   // [B][T][H]
                   float* __restrict__ out_alpha) {  // [B][T][N_SRC]
    const int t   = blockIdx.x;
    const int b   = blockIdx.y;
    const int tid = threadIdx.x;
    const int pos = pos_ptr ? *pos_ptr : N_SRC;
    const int j   = tid << 2;                       // float index within row

    // query chunk for this thread (L2-resident after first CTAs)
    const float4 q = *(const float4*)(wq + (size_t)pos * H + j);

    const size_t row  = ((size_t)b * T + t) * (size_t)H + j;   // routed layout too
    const size_t nstr = (size_t)B * T * H;                      // n stride in values

    float4 v[N_SRC];
    float  ss[N_SRC];   // partial sum of squares
    float  dq[N_SRC];   // partial q.v

    #pragma unroll
    for (int n = 0; n < N_SRC; n++) {
        const float4 x = *(const float4*)(values + row + (size_t)n * nstr);
        v[n] = x;
        ss[n] = x.x*x.x + x.y*x.y + x.z*x.z + x.w*x.w;
        dq[n] = q.x*x.x + q.y*x.y + q.z*x.z + q.w*x.w;
    }

    // warp-level reduction of all 16 partials
    #pragma unroll
    for (int n = 0; n < N_SRC; n++) {
        #pragma unroll
        for (int o = 16; o; o >>= 1) {
            ss[n] += __shfl_xor_sync(0xffffffffu, ss[n], o);
            dq[n] += __shfl_xor_sync(0xffffffffu, dq[n], o);
        }
    }

    __shared__ float red[16][16];   // [warp][2*n + {ss,dq}]
    __shared__ float tot[16];
    const int warp = tid >> 5, lane = tid & 31;
    if (lane == 0) {
        #pragma unroll
        for (int n = 0; n < N_SRC; n++) {
            red[warp][2*n]     = ss[n];
            red[warp][2*n + 1] = dq[n];
        }
    }
    __syncthreads();
    if (tid < 16) {
        float s = 0.f;
        #pragma unroll
        for (int w = 0; w < 16; w++) s += red[w][tid];
        tot[tid] = s;
    }
    __syncthreads();

    // redundant per-thread softmax over 8 scalars (cheap, avoids broadcast sync)
    float alpha[N_SRC];
    {
        const float inv_sqrt_h = rsqrtf((float)H);
        const float inv_h = 1.0f / (float)H;
        float sc[N_SRC];
        float m = -1e30f;
        #pragma unroll
        for (int n = 0; n < N_SRC; n++) {
            const float sumsq = tot[2*n];
            const float dotq  = tot[2*n + 1];
            const float inv   = rsqrtf(sumsq * inv_h + EPS);   // rms inverse
            sc[n] = dotq * inv * inv_sqrt_h + g_cbias[n];
            m = fmaxf(m, sc[n]);
        }
        float sum = 0.f;
        #pragma unroll
        for (int n = 0; n < N_SRC; n++) { sc[n] = __expf(sc[n] - m); sum += sc[n]; }
        const float r = 1.0f / sum;
        #pragma unroll
        for (int n = 0; n < N_SRC; n++) alpha[n] = sc[n] * r;
    }

    // routed = sum_n alpha_n * v_n  (data still in registers)
    float4 o;
    o.x = alpha[0]*v[0].x; o.y = alpha[0]*v[0].y; o.z = alpha[0]*v[0].z; o.w = alpha[0]*v[0].w;
    #pragma unroll
    for (int n = 1; n < N_SRC; n++) {
        o.x += alpha[n]*v[n].x;
        o.y += alpha[n]*v[n].y;
        o.z += alpha[n]*v[n].z;
        o.w += alpha[n]*v[n].w;
    }
    *(float4*)(out_routed + row) = o;

    if (tid < N_SRC)
        out_alpha[((size_t)b * T + t) * N_SRC + tid] = alpha[tid];
}

// ---------------------------------------------------------------------------
// kernel_launch
// inputs: [0] values f32 [8,4,2048,2048], [1] w_query f32 [12,2048],
//         [2] key_pos_bias f32 [12,2048], [3] position i32 scalar
// output: routed f32 [4,2048,2048] followed by alpha f32 [4,2048,8]
// ---------------------------------------------------------------------------
extern "C" void kernel_launch(void* const* d_in, const int* in_sizes, int n_in,
                              void* d_out, int out_size) {
    const float* values = (const float*)d_in[0];
    const float* wq     = (const float*)d_in[1];
    const float* bias   = (const float*)d_in[2];
    const int*   pos    = (n_in > 3) ? (const int*)d_in[3] : nullptr;

    float* out_routed = (float*)d_out;
    float* out_alpha  = (float*)d_out + (size_t)B * T * H;

    cbias_kernel<<<N_SRC, 256>>>(wq, bias, pos);

    dim3 grid(T, B);
    router_kernel<<<grid, THREADS>>>(values, wq, pos, out_routed, out_alpha);
}